// round 13
// baseline (speedup 1.0000x reference)
#include <cuda_runtime.h>
#include <math.h>

// Problem constants
#define DD 128
#define TT 512
#define HH 512

// 4 groups x 32 CTAs; group g owns batches [64g, 64g+64).
// CTA c owns h-columns [16c,16c+16) and z-columns [4c,4c+4).
#define NGROUP 4
#define CPG 32
#define MB 64
#define NCTA (NGROUP * CPG)
#define NTHREADS 256
#define KT 64
#define NTILE (HH / KT)          // 8 staged h tiles per step

// smem layout (floats):
//   Ws4: packed W_hh slice [k][tx] float4 {wr,wz,wn,wf}  -> 512*64
//   Wi4: packed W_ih slice [k][tx] float4 {wr,wz,wn,0}   -> 128*64
//   hs : ping-pong activation tiles (2 x 64x64)           -> 8192
#define SM_WS 0
#define SM_WI (SM_WS + HH * 64)
#define SM_HS (SM_WI + DD * 64)
#define SM_FLOATS (SM_HS + 2 * KT * MB)
#define SMEM_BYTES (SM_FLOATS * 4)          // 196,608 B

typedef unsigned long long u64;

__device__ __forceinline__ u64 pack2(float x) {
    u64 r; unsigned u = __float_as_uint(x);
    asm("mov.b64 %0, {%1, %1};" : "=l"(r) : "r"(u));
    return r;
}
__device__ __forceinline__ void fma2(u64 &acc, u64 a, u64 b) {
    asm("fma.rn.f32x2 %0, %1, %2, %0;" : "+l"(acc) : "l"(a), "l"(b));
}
__device__ __forceinline__ void unpack2(u64 v, float &lo, float &hi) {
    unsigned a, b;
    asm("mov.b64 {%0, %1}, %2;" : "=r"(a), "=r"(b) : "l"(v));
    lo = __uint_as_float(a); hi = __uint_as_float(b);
}

// Global state (zero-initialized at module load)
__device__ __align__(16) float g_hbuf[NGROUP * HH * MB];  // [g][k][b]
__device__ __align__(16) float g_zbuf[NGROUP * DD * MB];  // [g][col][b]
__device__ unsigned g_cnt[NGROUP];
__device__ volatile unsigned g_gen[NGROUP];

#define CP_COMMIT() asm volatile("cp.async.commit_group;\n" ::: "memory")
#define CP_WAIT(n)  asm volatile("cp.async.wait_group %0;\n" :: "n"(n) : "memory")

__device__ __forceinline__ void stage_async(float *dst, const float *src, int n4) {
    const float4 *s4 = (const float4 *)src;
    float4 *d4 = (float4 *)dst;
    for (int i = threadIdx.x; i < n4; i += NTHREADS) {
        unsigned sa = (unsigned)__cvta_generic_to_shared(d4 + i);
        asm volatile("cp.async.cg.shared.global [%0], [%1], 16;\n"
                     :: "r"(sa), "l"(s4 + i) : "memory");
    }
}

// Sense-reversing group barrier across 32 co-resident CTAs.
// Release-side fence only: cross-CTA data reads after the barrier go through
// L2 (cp.async.cg), so no L1-invalidate acquire is needed.
__device__ __forceinline__ void group_barrier(int g, unsigned &next_gen) {
    __syncthreads();
    if (threadIdx.x == 0) {
        __threadfence();                       // publish our global writes
        unsigned prev = atomicAdd(&g_cnt[g], 1u);
        if (prev == CPG - 1) {
            g_cnt[g] = 0;
            __threadfence();
            g_gen[g] = next_gen;               // release
        } else {
            while ((int)(g_gen[g] - next_gen) < 0) { }
        }
    }
    next_gen++;
    __syncthreads();
}

__device__ __forceinline__ float fast_sigmoid(float x) {
    return __fdividef(1.0f, 1.0f + __expf(-x));
}
__device__ __forceinline__ float fast_tanh(float y) {
    const float a = fabsf(y);
    const float e = __expf(-2.0f * a);
    const float t = __fdividef(1.0f - e, 1.0f + e);
    return copysignf(t, y);
}

__global__ __launch_bounds__(NTHREADS, 1)
void gru_decoder_kernel(const float *__restrict__ z_in,
                        const float *__restrict__ W_ih,
                        const float *__restrict__ W_hh,
                        const float *__restrict__ b_ih,
                        const float *__restrict__ b_hh,
                        const float *__restrict__ fc_W,
                        const float *__restrict__ fc_b,
                        float *__restrict__ out) {
    extern __shared__ float sm[];
    float *Ws4 = sm + SM_WS;
    float *Wi4 = sm + SM_WI;
    float *hs  = sm + SM_HS;

    const int tid = threadIdx.x;
    const int c = blockIdx.x & (CPG - 1);
    const int g = blockIdx.x >> 5;
    const int tx = tid & 15;              // owned j (within the 16-slice)
    const int ty = tid >> 4;              // 0..15: batch quad {4ty..4ty+3}
    const int jg = 16 * c + tx;
    // delta duty: column cd = tx>>2 (matches wf folded into Ws4 .w slot),
    // batch b_d = 4*ty + (tx&3)  (bijective over 64 per column)
    const int cd = tx >> 2;
    const int b_d = 4 * ty + (tx & 3);
    const int colg = 4 * c + cd;
    const int b0 = g * MB;

    // ---- stage + pack weight slices (one-time) ----
    for (int r = 0; r < 48; ++r) {
        const int gate = r >> 4, txv = r & 15;
        const float *src = W_hh + (gate * HH + 16 * c + txv) * HH;
        for (int k = tid; k < HH; k += NTHREADS)
            Ws4[k * 64 + txv * 4 + gate] = src[k];
    }
    for (int r = 0; r < 48; ++r) {
        const int gate = r >> 4, txv = r & 15;
        const float *src = W_ih + (gate * HH + 16 * c + txv) * DD;
        for (int k = tid; k < DD; k += NTHREADS)
            Wi4[k * 64 + txv * 4 + gate] = src[k];
    }
    // .w slots: Ws4 gets fc_W (column 4c + (tx>>2)); Wi4 zero
    for (int idx = tid; idx < HH * 16; idx += NTHREADS) {
        const int k = idx >> 4, txv = idx & 15;
        Ws4[k * 64 + txv * 4 + 3] = fc_W[(4 * c + (txv >> 2)) * HH + k];
    }
    for (int idx = tid; idx < DD * 16; idx += NTHREADS) Wi4[idx * 4 + 3] = 0.f;

    // ---- per-thread constants ----
    const float br_s  = b_ih[jg] + b_hh[jg];
    const float bz_s  = b_ih[HH + jg] + b_hh[HH + jg];
    const float bin_s = b_ih[2 * HH + jg];
    const float bhn_s = b_hh[2 * HH + jg];
    const float fcb   = fc_b[colg];

    // ---- z0 init ----
    float z_reg = z_in[(b0 + b_d) * (DD * TT) + colg * TT];
    g_zbuf[(g * DD + colg) * MB + b_d] = z_reg;
    out[(b0 + b_d) * (DD * TT) + colg * TT] = z_reg;

    float hprev[4] = {0.f, 0.f, 0.f, 0.f};

    unsigned next_gen = g_gen[g] + 1;  // stable snapshot: release needs all arrivals
    group_barrier(g, next_gen);        // zbuf visible group-wide

    const float *hbuf = g_hbuf + g * HH * MB;
    const float *zbuf = g_zbuf + g * DD * MB;
    const float4 *Wsv = (const float4 *)Ws4;
    const float4 *Wiv = (const float4 *)Wi4;

    const u64 br2 = pack2(br_s), bz2 = pack2(bz_s);
    const u64 bhn2 = pack2(bhn_s), bin2 = pack2(bin_s);

    for (int t = 1; t <= TT; ++t) {
        u64 accr01 = br2,  accr23 = br2;
        u64 accz01 = bz2,  accz23 = bz2;
        u64 acchn01 = bhn2, acchn23 = bhn2;
        u64 accin01 = bin2, accin23 = bin2;
        float dacc = fcb;

        // ---- h-pass: gh_t and delta_{t-1}, double-buffered cp.async tiles ----
        if (t > 1) {
            stage_async(hs, hbuf, KT * MB / 4);
            CP_COMMIT();
            for (int it = 0; it < NTILE; ++it) {
                if (it + 1 < NTILE) {
                    stage_async(hs + ((it + 1) & 1) * (KT * MB),
                                hbuf + (it + 1) * (KT * MB), KT * MB / 4);
                    CP_COMMIT();
                    CP_WAIT(1);
                } else {
                    CP_WAIT(0);
                }
                __syncthreads();   // tile `it` visible to all threads

                const float *hb = hs + (it & 1) * (KT * MB);
                const float4 *wp = Wsv + it * (KT * 16);

#pragma unroll 8
                for (int kk = 0; kk < KT; ++kk) {
                    const float4 w4 = wp[kk * 16 + tx];
                    const ulonglong2 hq =
                        *(const ulonglong2 *)(hb + kk * MB + 4 * ty);
                    const float hd = hb[kk * MB + b_d];
                    const u64 wr2 = pack2(w4.x);
                    const u64 wz2 = pack2(w4.y);
                    const u64 wn2 = pack2(w4.z);
                    fma2(accr01,  wr2, hq.x); fma2(accr23,  wr2, hq.y);
                    fma2(accz01,  wz2, hq.x); fma2(accz23,  wz2, hq.y);
                    fma2(acchn01, wn2, hq.x); fma2(acchn23, wn2, hq.y);
                    dacc += w4.w * hd;
                }
                __syncthreads();   // reads done before buffer is re-staged
            }
            z_reg += dacc;
            g_zbuf[(g * DD + colg) * MB + b_d] = z_reg;
            out[(b0 + b_d) * (DD * TT) + colg * TT + (t - 1)] = z_reg;
        }

        group_barrier(g, next_gen);   // z_{t-1} complete group-wide

        if (t < TT) {
            // ---- z-pass: gi_t over full z_{t-1} ----
            stage_async(hs, zbuf, DD * MB / 4);
            CP_COMMIT();
            CP_WAIT(0);
            __syncthreads();

#pragma unroll 8
            for (int kk = 0; kk < DD; ++kk) {
                const float4 w4 = Wiv[kk * 16 + tx];
                const ulonglong2 xq =
                    *(const ulonglong2 *)(hs + kk * MB + 4 * ty);
                const u64 wr2 = pack2(w4.x);
                const u64 wz2 = pack2(w4.y);
                const u64 wn2 = pack2(w4.z);
                fma2(accr01,  wr2, xq.x); fma2(accr23,  wr2, xq.y);
                fma2(accz01,  wz2, xq.x); fma2(accz23,  wz2, xq.y);
                fma2(accin01, wn2, xq.x); fma2(accin23, wn2, xq.y);
            }

            // ---- gates + h update (owned slice in registers) ----
            float ar[4], az[4], ahn[4], ain[4];
            unpack2(accr01, ar[0], ar[1]);   unpack2(accr23, ar[2], ar[3]);
            unpack2(accz01, az[0], az[1]);   unpack2(accz23, az[2], az[3]);
            unpack2(acchn01, ahn[0], ahn[1]); unpack2(acchn23, ahn[2], ahn[3]);
            unpack2(accin01, ain[0], ain[1]); unpack2(accin23, ain[2], ain[3]);
#pragma unroll
            for (int i = 0; i < 4; ++i) {
                const float r  = fast_sigmoid(ar[i]);
                const float zg = fast_sigmoid(az[i]);
                const float n  = fast_tanh(ain[i] + r * ahn[i]);
                const float h  = (1.0f - zg) * n + zg * hprev[i];
                hprev[i] = h;
                g_hbuf[(g * HH + jg) * MB + 4 * ty + i] = h;
            }
        }

        group_barrier(g, next_gen);   // h_t complete group-wide
    }
}

extern "C" void kernel_launch(void* const* d_in, const int* in_sizes, int n_in,
                              void* d_out, int out_size) {
    (void)in_sizes; (void)n_in; (void)out_size;
    const float *z    = (const float *)d_in[0];
    // d_in[1] = e (unused by the reference computation)
    const float *W_ih = (const float *)d_in[2];
    const float *W_hh = (const float *)d_in[3];
    const float *b_ih = (const float *)d_in[4];
    const float *b_hh = (const float *)d_in[5];
    const float *fc_W = (const float *)d_in[6];
    const float *fc_b = (const float *)d_in[7];
    float *out = (float *)d_out;

    cudaFuncSetAttribute(gru_decoder_kernel,
                         cudaFuncAttributeMaxDynamicSharedMemorySize, SMEM_BYTES);
    gru_decoder_kernel<<<NCTA, NTHREADS, SMEM_BYTES>>>(
        z, W_ih, W_hh, b_ih, b_hh, fc_W, fc_b, out);
}